// round 8
// baseline (speedup 1.0000x reference)
#include <cuda_runtime.h>
#include <cuda_fp16.h>
#include <cstdint>

#define DD  1024
#define NB  64
#define NKK 512
#define MROWS (NB * NKK)          // 32768 flattened z-rows

// ---------------- device scratch (no allocs allowed) ----------------
__device__ __half g_wzT[DD * DD];            // w_z transposed fp16: [e][d]
__device__ float  g_c[16][NB * DD];          // split-K partials of c[b,e]
__device__ float  g_qp[8 * MROWS];           // partial q per n-tile (8 nt)

// ---------------- helpers ----------------
static __device__ __forceinline__ uint32_t smem_u32(const void* p) {
    uint32_t a;
    asm("{ .reg .u64 t; cvta.to.shared.u64 t, %1; cvt.u32.u64 %0, t; }" : "=r"(a) : "l"(p));
    return a;
}
#define CP16(dst, src) \
    asm volatile("cp.async.cg.shared.global [%0], [%1], 16;" :: "r"(dst), "l"(src))
#define CP_COMMIT() asm volatile("cp.async.commit_group;" ::: "memory")
#define CP_WAIT(n)  asm volatile("cp.async.wait_group %0;" :: "n"(n) : "memory")

#define LDSM_X4(r0, r1, r2, r3, addr) \
    asm volatile("ldmatrix.sync.aligned.m8n8.x4.shared.b16 {%0,%1,%2,%3}, [%4];" \
        : "=r"(r0), "=r"(r1), "=r"(r2), "=r"(r3) : "r"(addr))

#define MMA16816(d, a, b0, b1) \
    asm volatile("mma.sync.aligned.m16n8k16.row.col.f32.f16.f16.f32 " \
        "{%0,%1,%2,%3}, {%4,%5,%6,%7}, {%8,%9}, {%0,%1,%2,%3};" \
        : "+f"((d)[0]), "+f"((d)[1]), "+f"((d)[2]), "+f"((d)[3]) \
        : "r"((a)[0]), "r"((a)[1]), "r"((a)[2]), "r"((a)[3]), "r"(b0), "r"(b1))

// exact identity tanh(x) = 1 - 2/(e^{2x}+1), via ex2.approx + rcp.approx (~1e-6)
static __device__ __forceinline__ float fast_tanh(float x) {
    float e;
    asm("ex2.approx.f32 %0, %1;" : "=f"(e) : "f"(x * 2.885390081777927f)); // 2*log2(e)
    float r;
    asm("rcp.approx.f32 %0, %1;" : "=f"(r) : "f"(e + 1.0f));
    return fmaf(-2.0f, r, 1.0f);
}

// ---------------- SMEM layout of the main kernel (XOR-swizzled 128B rows) --------
static constexpr int SA_ST   = 128 * 128;              // 16 KB per stage (fp16)
static constexpr int SB_ST   = 128 * 128;              // 16 KB per stage
static constexpr int OFF_SA  = 0;
static constexpr int OFF_SB  = 3 * SA_ST;              // 49152
static constexpr int OFF_C   = OFF_SB + 3 * SB_ST;     // 98304
static constexpr int OFF_BI  = OFF_C + 512;
static constexpr int OFF_QB  = OFF_BI + 512;
static constexpr int SMEM_MAIN = OFF_QB + 2048;        // 101376

// ---------------- prep kernel: w_z transpose->fp16 | split-K cvec ----------------
// blocks [0,1024): transpose ; [1024,2048): cvec partials (d-split by 16)
__global__ void __launch_bounds__(256) prep_kernel(const float* __restrict__ x,
                                                   const float* __restrict__ W) {
    __shared__ float psm[33 * 32];     // union: 32x33 f32 tile | 4 x 64 u-slice
    const int bid = blockIdx.x, t = threadIdx.x;

    if (bid < 1024) {                 // ---- transpose w_z -> g_wzT fp16 ----
        float (*tile)[33] = reinterpret_cast<float (*)[33]>(psm);
        const int d0 = (bid & 31) * 32, e0 = (bid >> 5) * 32;
        const int tx = t & 31, ty = t >> 5;          // (32, 8)
#pragma unroll
        for (int i = 0; i < 32; i += 8)
            tile[ty + i][tx] = W[(size_t)(d0 + ty + i) * DD + e0 + tx];
        __syncthreads();
#pragma unroll
        for (int i = 0; i < 32; i += 8)
            g_wzT[(size_t)(e0 + ty + i) * DD + d0 + tx] = __float2half(tile[tx][ty + i]);
    } else {                          // ---- cvec partial: sum over 64 d's ----
        const int idx = bid - 1024;                  // 1024 blocks
        const int e  = (idx & 3) * 256 + t;          // e-chunk
        const int b0 = ((idx >> 2) & 15) * 4;        // 4 batches
        const int kq = idx >> 6;                     // d-sixteenth (64 d's)
        float (*us)[64] = reinterpret_cast<float (*)[64]>(psm);
        if (t < 256) {
            int j = t >> 6, d = t & 63;
            us[j][d] = x[(size_t)(b0 + j) * 513 * DD + kq * 64 + d];
        }
        __syncthreads();
        const float* wu = W + (size_t)DD * DD + (size_t)kq * 64 * DD;
        float a0 = 0, a1 = 0, a2 = 0, a3 = 0;
#pragma unroll 8
        for (int d = 0; d < 64; d++) {
            float w = __ldg(wu + (size_t)d * DD + e);
            a0 = fmaf(us[0][d], w, a0);
            a1 = fmaf(us[1][d], w, a1);
            a2 = fmaf(us[2][d], w, a2);
            a3 = fmaf(us[3][d], w, a3);
        }
        g_c[kq][(b0 + 0) * DD + e] = a0;
        g_c[kq][(b0 + 1) * DD + e] = a1;
        g_c[kq][(b0 + 2) * DD + e] = a2;
        g_c[kq][(b0 + 3) * DD + e] = a3;
    }
}

// ---------------- kernel 1: fused GEMM(mma.16816) + tanh + bias-dot ----------------
// grid = 2048: mtile(256) x ntile(8). CTA 256 thr (2 CTAs/SM): M=128 x N=128, K=1024.
// Warp grid 2x4, warp tile m64n32. A: fp32 LDG -> cvt -> STS. B: cp.async fp16.
__global__ void __launch_bounds__(256, 2) main_kernel(const float* __restrict__ x,
                                                      const float* __restrict__ bias) {
    extern __shared__ char smem[];
    const uint32_t sb = smem_u32(smem);
    const int tid  = threadIdx.x;
    const int w    = tid >> 5, lane = tid & 31;
    const int wm   = w >> 2,  wn   = w & 3;
    const int nt   = blockIdx.x & 7;
    const int m0   = (blockIdx.x >> 3) * 128;
    const int b    = m0 >> 9;

    float* c_sm  = reinterpret_cast<float*>(smem + OFF_C);
    float* bi_sm = reinterpret_cast<float*>(smem + OFF_BI);
    if (tid < 128) {
        const int off = b * DD + nt * 128 + tid;
        float s0 = 0.f, s1 = 0.f, s2 = 0.f, s3 = 0.f;
#pragma unroll
        for (int i = 0; i < 4; i++) {
            s0 += g_c[4 * i + 0][off];
            s1 += g_c[4 * i + 1][off];
            s2 += g_c[4 * i + 2][off];
            s3 += g_c[4 * i + 3][off];
        }
        c_sm[tid]  = (s0 + s1) + (s2 + s3);
        bi_sm[tid] = bias[nt * 128 + tid];
    }

    const float*  Ax = x + (size_t)(b * 513 + 1 + (m0 & 511)) * DD;   // 128 z-rows
    const __half* Bb = g_wzT + (size_t)nt * 128 * DD;

    // A geometry: 8 float4 per thread per chunk (rows (tid>>4)+j*16, col4 tid&15)
    const int aR0 = tid >> 4;
    const int aC4 = tid & 15;

    auto ldgA = [&](int kc, float4* apf) {
#pragma unroll
        for (int j = 0; j < 8; j++)
            apf[j] = __ldg(reinterpret_cast<const float4*>(Ax + (size_t)(aR0 + j * 16) * DD + kc * 64) + aC4);
    };
    auto stsA = [&](int s, const float4* apf) {
#pragma unroll
        for (int j = 0; j < 8; j++) {
            const int row = aR0 + j * 16;
            __half2 h0 = __floats2half2_rn(apf[j].x, apf[j].y);
            __half2 h1 = __floats2half2_rn(apf[j].z, apf[j].w);
            uint32_t u0 = *reinterpret_cast<const uint32_t*>(&h0);
            uint32_t u1 = *reinterpret_cast<const uint32_t*>(&h1);
            uint32_t dst = sb + OFF_SA + s * SA_ST + row * 128
                         + ((((aC4 >> 1) ^ (row & 7)) << 4) + ((aC4 & 1) << 3));
            asm volatile("st.shared.v2.b32 [%0], {%1, %2};" :: "r"(dst), "r"(u0), "r"(u1) : "memory");
        }
    };
    auto issueB = [&](int kc, int s) {
#pragma unroll
        for (int j = 0; j < 4; j++) {   // B: 128 rows x 8 segs = 1024 x 16B
            int i = tid + j * 256;
            int row = i >> 3, v = i & 7;
            uint32_t dst = sb + OFF_SB + s * SB_ST + row * 128 + ((v ^ (row & 7)) << 4);
            CP16(dst, Bb + (size_t)row * DD + kc * 64 + v * 8);
        }
        CP_COMMIT();
    };

    float acc[4][4][4];     // [mi][nj][reg], warp tile m64n32
#pragma unroll
    for (int mi = 0; mi < 4; mi++)
#pragma unroll
        for (int nj = 0; nj < 4; nj++)
#pragma unroll
            for (int r = 0; r < 4; r++) acc[mi][nj][r] = 0.0f;

    // per-lane ldmatrix geometry
    const int aRow  = wm * 64 + (lane & 15);            // + mi*16
    const int aBit  = lane >> 4;
    const int aSw   = aRow & 7;
    const int bRowL = (lane & 7) + ((lane >> 4) << 3);  // + wn*32 + g*16
    const int bBit  = (lane >> 3) & 1;

    // prologue
    float4 apf[8];
    ldgA(0, apf);
    stsA(0, apf);
    ldgA(1, apf);
    issueB(0, 0);
    issueB(1, 1);

    for (int kc = 0; kc < 16; kc++) {
        // STS A(kc+1) BEFORE the barrier: stage (kc+1)%3 untouched by laggards.
        if (kc < 15) stsA((kc + 1) % 3, apf);
        if (kc == 15) { CP_WAIT(0); } else { CP_WAIT(1); }
        __syncthreads();
        if (kc < 14) { ldgA(kc + 2, apf); issueB(kc + 2, (kc + 2) % 3); }

        const int s = kc % 3;
        const uint32_t aBase = sb + OFF_SA + s * SA_ST + aRow * 128;
        const uint32_t bBase = sb + OFF_SB + s * SB_ST;
#pragma unroll
        for (int ks = 0; ks < 4; ks++) {
            uint32_t a[4][4];
#pragma unroll
            for (int mi = 0; mi < 4; mi++) {
                uint32_t addr = aBase + mi * (16 * 128) + ((((ks * 2) + aBit) ^ aSw) << 4);
                LDSM_X4(a[mi][0], a[mi][1], a[mi][2], a[mi][3], addr);
            }
            uint32_t bf[4][2];
#pragma unroll
            for (int g = 0; g < 2; g++) {
                const int nrow = wn * 32 + g * 16 + bRowL;
                uint32_t addr = bBase + nrow * 128 + ((((ks * 2) + bBit) ^ (nrow & 7)) << 4);
                LDSM_X4(bf[2 * g][0], bf[2 * g][1], bf[2 * g + 1][0], bf[2 * g + 1][1], addr);
            }
#pragma unroll
            for (int mi = 0; mi < 4; mi++)
#pragma unroll
                for (int nj = 0; nj < 4; nj++)
                    MMA16816(acc[mi][nj], a[mi], bf[nj][0], bf[nj][1]);
        }
    }

    // ---- epilogue (registers): +c -> tanh -> *bias -> row partials ----
    const int colb = wn * 32 + 2 * (lane & 3);
    float p[8];
#pragma unroll
    for (int i = 0; i < 8; i++) p[i] = 0.0f;
#pragma unroll
    for (int mi = 0; mi < 4; mi++)
#pragma unroll
        for (int nj = 0; nj < 4; nj++) {
            const int c0 = colb + nj * 8;
            p[2 * mi + 0] = fmaf(fast_tanh(acc[mi][nj][0] + c_sm[c0]),     bi_sm[c0],     p[2 * mi + 0]);
            p[2 * mi + 0] = fmaf(fast_tanh(acc[mi][nj][1] + c_sm[c0 + 1]), bi_sm[c0 + 1], p[2 * mi + 0]);
            p[2 * mi + 1] = fmaf(fast_tanh(acc[mi][nj][2] + c_sm[c0]),     bi_sm[c0],     p[2 * mi + 1]);
            p[2 * mi + 1] = fmaf(fast_tanh(acc[mi][nj][3] + c_sm[c0 + 1]), bi_sm[c0 + 1], p[2 * mi + 1]);
        }
#pragma unroll
    for (int i = 0; i < 8; i++) {
        p[i] += __shfl_xor_sync(0xffffffffu, p[i], 1);
        p[i] += __shfl_xor_sync(0xffffffffu, p[i], 2);
    }
    float* qb = reinterpret_cast<float*>(smem + OFF_QB);
    if ((lane & 3) == 0) {
        const int r = wm * 64 + (lane >> 2);
#pragma unroll
        for (int mi = 0; mi < 4; mi++) {
            qb[wn * 128 + r + mi * 16 + 0] = p[2 * mi + 0];
            qb[wn * 128 + r + mi * 16 + 8] = p[2 * mi + 1];
        }
    }
    __syncthreads();
    if (tid < 128) {
        float s = qb[tid] + qb[128 + tid] + qb[256 + tid] + qb[384 + tid];
        g_qp[(size_t)nt * MROWS + m0 + tid] = s;
    }
}

// ---------------- kernel 2: softmax over k=512 per batch ----------------
__global__ void __launch_bounds__(512) softmax_kernel(float* __restrict__ out) {
    __shared__ float sred[16];
    __shared__ float sbc;
    const int b = blockIdx.x, t = threadIdx.x;
    const int wid = t >> 5, lid = t & 31;
    const int idx = b * NKK + t;
    float v = 0.f;
#pragma unroll
    for (int i = 0; i < 8; i++) v += g_qp[(size_t)i * MROWS + idx];

    float m = v;
#pragma unroll
    for (int o = 16; o; o >>= 1) m = fmaxf(m, __shfl_xor_sync(0xffffffffu, m, o));
    if (lid == 0) sred[wid] = m;
    __syncthreads();
    if (wid == 0) {
        float mm = (lid < 16) ? sred[lid] : -1e30f;
#pragma unroll
        for (int o = 16; o; o >>= 1) mm = fmaxf(mm, __shfl_xor_sync(0xffffffffu, mm, o));
        if (lid == 0) sbc = mm;
    }
    __syncthreads();
    const float M = sbc;
    float e;
    asm("ex2.approx.f32 %0, %1;" : "=f"(e) : "f"((v - M) * 1.4426950408889634f));
    float s = e;
#pragma unroll
    for (int o = 16; o; o >>= 1) s += __shfl_xor_sync(0xffffffffu, s, o);
    __syncthreads();
    if (lid == 0) sred[wid] = s;
    __syncthreads();
    if (wid == 0) {
        float ss = (lid < 16) ? sred[lid] : 0.f;
#pragma unroll
        for (int o = 16; o; o >>= 1) ss += __shfl_xor_sync(0xffffffffu, ss, o);
        if (lid == 0) sbc = ss;
    }
    __syncthreads();
    out[idx] = e / sbc;
}

// ---------------- launch ----------------
extern "C" void kernel_launch(void* const* d_in, const int* in_sizes, int n_in,
                              void* d_out, int out_size) {
    const float* x    = (const float*)d_in[0];
    const float* W    = (const float*)d_in[1];
    const float* bias = (const float*)d_in[2];
    float* out = (float*)d_out;

    cudaFuncSetAttribute(main_kernel, cudaFuncAttributeMaxDynamicSharedMemorySize, SMEM_MAIN);

    prep_kernel<<<2048, 256>>>(x, W);
    main_kernel<<<2048, 256, SMEM_MAIN>>>(x, bias);
    softmax_kernel<<<64, 512>>>(out);
}